// round 1
// baseline (speedup 1.0000x reference)
#include <cuda_runtime.h>
#include <cuda_bf16.h>
#include <cstdint>

// Problem constants: z1, z2 are (4096, 256) fp32; interleaved Z is (8192, 256).
#define D      256
#define NROWS  8192
#define TILE   128
#define SA     132           // padded row stride in 32-bit words (264 bf16) -> conflict-free frag loads
#define JTILES (NROWS / TILE)
#define SPLIT  4             // J-dimension split across blockIdx.y

// Scratch (device globals; no allocation in kernel_launch)
__device__ __nv_bfloat16 g_Zb[NROWS * D];   // normalized rows, bf16, interleaved
__device__ float g_pos[NROWS];              // log(pos_i) = 2 * dot(z_i, z_{i^1}) in fp32
__device__ float g_rowsum[NROWS];           // sum_j exp(2 * z_i . z_j)

// ---------------------------------------------------------------------------
// prep: normalize each pair of rows (fp32), emit bf16 Z, exact fp32 log(pos),
// and zero the rowsum accumulators. One block per pair, 256 threads (== D).
// ---------------------------------------------------------------------------
__global__ void prep_kernel(const float* __restrict__ z1, const float* __restrict__ z2) {
    const int p   = blockIdx.x;      // pair index 0..4095
    const int tid = threadIdx.x;     // 0..255 == D
    float a = z1[p * D + tid];
    float b = z2[p * D + tid];
    float s1 = a * a, s2 = b * b, s3 = a * b;
    #pragma unroll
    for (int off = 16; off; off >>= 1) {
        s1 += __shfl_xor_sync(0xffffffffu, s1, off);
        s2 += __shfl_xor_sync(0xffffffffu, s2, off);
        s3 += __shfl_xor_sync(0xffffffffu, s3, off);
    }
    __shared__ float sh[24];
    const int w = tid >> 5, lane = tid & 31;
    if (lane == 0) { sh[w] = s1; sh[8 + w] = s2; sh[16 + w] = s3; }
    __syncthreads();
    if (tid == 0) {
        float t1 = 0.f, t2 = 0.f, t3 = 0.f;
        #pragma unroll
        for (int i = 0; i < 8; ++i) { t1 += sh[i]; t2 += sh[8 + i]; t3 += sh[16 + i]; }
        float inv1 = 1.0f / fmaxf(sqrtf(t1), 1e-12f);
        float inv2 = 1.0f / fmaxf(sqrtf(t2), 1e-12f);
        float dp = t3 * inv1 * inv2;           // dot of normalized rows, fp32
        g_pos[2 * p]     = 2.0f * dp;          // log(exp(dot / 0.5))
        g_pos[2 * p + 1] = 2.0f * dp;
        g_rowsum[2 * p]     = 0.0f;
        g_rowsum[2 * p + 1] = 0.0f;
        sh[0] = inv1; sh[1] = inv2;
    }
    __syncthreads();
    const float inv1 = sh[0], inv2 = sh[1];
    g_Zb[(2 * p)     * D + tid] = __float2bfloat16(a * inv1);
    g_Zb[(2 * p + 1) * D + tid] = __float2bfloat16(b * inv2);
}

// ---------------------------------------------------------------------------
// GEMM + exp + row-reduce. C[i][j] = z_i . z_j via bf16 mma.sync m16n8k16,
// rowsum_i += sum_j exp(2*C[i][j]). Tile: 128(I) x 128(J), K=256.
// 8 warps: warp grid 4(m) x 2(n), warp tile 32m x 64n.
// ---------------------------------------------------------------------------
__device__ __forceinline__ void mma16816(float c[4], const uint32_t a[4], const uint32_t b[2]) {
    asm volatile(
        "mma.sync.aligned.m16n8k16.row.col.f32.bf16.bf16.f32 "
        "{%0,%1,%2,%3}, {%4,%5,%6,%7}, {%8,%9}, {%0,%1,%2,%3};\n"
        : "+f"(c[0]), "+f"(c[1]), "+f"(c[2]), "+f"(c[3])
        : "r"(a[0]), "r"(a[1]), "r"(a[2]), "r"(a[3]), "r"(b[0]), "r"(b[1]));
}

__device__ __forceinline__ float ex2(float x) {
    float y;
    asm("ex2.approx.f32 %0, %1;" : "=f"(y) : "f"(x));
    return y;
}

extern __shared__ uint32_t smem_dyn[];

__global__ void __launch_bounds__(256, 1) gemm_kernel() {
    uint32_t* As     = smem_dyn;                    // 128 rows x 132 words (padded)
    uint32_t* Bs     = smem_dyn + TILE * SA;
    float*    rowAcc = (float*)(smem_dyn + 2 * TILE * SA);

    const int tid = threadIdx.x;
    const int i0  = blockIdx.x * TILE;

    // Load A tile (persistent across all J tiles), padded rows: 33 uint4 per row.
    {
        const uint4* gz  = (const uint4*)g_Zb;      // 32 uint4 per logical row
        uint4*       As4 = (uint4*)As;
        #pragma unroll
        for (int it = 0; it < 16; ++it) {
            int idx = tid + it * 256;               // 0..4095
            int r = idx >> 5, c = idx & 31;
            As4[r * 33 + c] = gz[(i0 + r) * 32 + c];
        }
    }
    if (tid < TILE) rowAcc[tid] = 0.0f;

    const int lane  = tid & 31;
    const int wid   = tid >> 5;
    const int gg    = lane >> 2;    // group id  (0..7)
    const int tt    = lane & 3;     // thread-in-group (0..3)
    const int warpM = wid & 3;      // 0..3 -> 32-row stripe
    const int warpN = wid >> 2;     // 0..1 -> 64-col stripe

    const int jtBeg = blockIdx.y * (JTILES / SPLIT);
    const int jtEnd = jtBeg + (JTILES / SPLIT);

    for (int jt = jtBeg; jt < jtEnd; ++jt) {
        __syncthreads();   // previous iter's reads (and initial A store / rowAcc zero) complete
        {
            const uint4* gz  = (const uint4*)g_Zb;
            uint4*       Bs4 = (uint4*)Bs;
            const int j0 = jt * TILE;
            #pragma unroll
            for (int it = 0; it < 16; ++it) {
                int idx = tid + it * 256;
                int r = idx >> 5, c = idx & 31;
                Bs4[r * 33 + c] = gz[(j0 + r) * 32 + c];
            }
        }
        __syncthreads();

        float c[2][8][4];
        #pragma unroll
        for (int ma = 0; ma < 2; ++ma)
            #pragma unroll
            for (int na = 0; na < 8; ++na)
                #pragma unroll
                for (int q = 0; q < 4; ++q) c[ma][na][q] = 0.0f;

        #pragma unroll 4
        for (int ks = 0; ks < 16; ++ks) {
            uint32_t a[2][4];
            #pragma unroll
            for (int ma = 0; ma < 2; ++ma) {
                const uint32_t* p = As + (warpM * 32 + ma * 16 + gg) * SA + ks * 8 + tt;
                a[ma][0] = p[0];            // (row g,   k 2t..2t+1)
                a[ma][2] = p[4];            // (row g,   k 2t+8..)
                a[ma][1] = p[8 * SA];       // (row g+8, k 2t..)
                a[ma][3] = p[8 * SA + 4];   // (row g+8, k 2t+8..)
            }
            uint32_t b[8][2];
            #pragma unroll
            for (int na = 0; na < 8; ++na) {
                const uint32_t* p = Bs + (warpN * 64 + na * 8 + gg) * SA + ks * 8 + tt;
                b[na][0] = p[0];            // (n g, k 2t..)
                b[na][1] = p[4];            // (n g, k 2t+8..)
            }
            #pragma unroll
            for (int ma = 0; ma < 2; ++ma)
                #pragma unroll
                for (int na = 0; na < 8; ++na)
                    mma16816(c[ma][na], a[ma], b[na]);
        }

        // Epilogue: exp(2*dot) = 2^(dot * 2/ln2), row-reduce across n.
        const float LOG2E2 = 2.8853900817779268f;   // 2 / ln(2)
        #pragma unroll
        for (int ma = 0; ma < 2; ++ma) {
            float s0 = 0.f, s1 = 0.f;
            #pragma unroll
            for (int na = 0; na < 8; ++na) {
                s0 += ex2(c[ma][na][0] * LOG2E2) + ex2(c[ma][na][1] * LOG2E2);
                s1 += ex2(c[ma][na][2] * LOG2E2) + ex2(c[ma][na][3] * LOG2E2);
            }
            // reduce across the 4 lanes (tt) sharing each row
            s0 += __shfl_xor_sync(0xffffffffu, s0, 1);
            s0 += __shfl_xor_sync(0xffffffffu, s0, 2);
            s1 += __shfl_xor_sync(0xffffffffu, s1, 1);
            s1 += __shfl_xor_sync(0xffffffffu, s1, 2);
            if (tt == 0) {
                atomicAdd(&rowAcc[warpM * 32 + ma * 16 + gg],     s0);
                atomicAdd(&rowAcc[warpM * 32 + ma * 16 + 8 + gg], s1);
            }
        }
    }
    __syncthreads();
    if (tid < TILE) atomicAdd(&g_rowsum[i0 + tid], rowAcc[tid]);
}

// ---------------------------------------------------------------------------
// Final reduction: loss = mean_i [ log(rowsum_i - e^2 + 1e-8) - log(pos_i) ]
// ---------------------------------------------------------------------------
__global__ void loss_kernel(float* __restrict__ out) {
    const float E2 = 7.3890560989306495f;   // exp(2) == diag term
    float acc = 0.0f;
    for (int i = threadIdx.x; i < NROWS; i += 256)
        acc += logf(g_rowsum[i] - E2 + 1e-8f) - g_pos[i];
    #pragma unroll
    for (int off = 16; off; off >>= 1)
        acc += __shfl_xor_sync(0xffffffffu, acc, off);
    __shared__ float sh[8];
    if ((threadIdx.x & 31) == 0) sh[threadIdx.x >> 5] = acc;
    __syncthreads();
    if (threadIdx.x == 0) {
        float t = 0.f;
        #pragma unroll
        for (int i = 0; i < 8; ++i) t += sh[i];
        out[0] = t * (1.0f / (float)NROWS);
    }
}

// ---------------------------------------------------------------------------
extern "C" void kernel_launch(void* const* d_in, const int* in_sizes, int n_in,
                              void* d_out, int out_size) {
    const float* z1 = (const float*)d_in[0];
    const float* z2 = (const float*)d_in[1];
    float* out = (float*)d_out;

    prep_kernel<<<NROWS / 2, 256>>>(z1, z2);

    const size_t smemBytes = (size_t)(2 * TILE * SA) * sizeof(uint32_t) + TILE * sizeof(float);
    cudaFuncSetAttribute(gemm_kernel, cudaFuncAttributeMaxDynamicSharedMemorySize, (int)smemBytes);
    dim3 grid(NROWS / TILE, SPLIT);
    gemm_kernel<<<grid, 256, smemBytes>>>();

    loss_kernel<<<1, 256>>>(out);
}

// round 3
// speedup vs baseline: 1.2418x; 1.2418x over previous
#include <cuda_runtime.h>
#include <cuda_bf16.h>
#include <cstdint>

// z1, z2: (4096, 256) fp32. Interleaved normalized Z: (8192, 256), quantized e4m3.
// loss = mean_i [ log(sum_j exp(2 z_i.z_j) - e^2 + 1e-8) - 2 z_i.z_{i^1} ]
#define D        256
#define NROWS    8192
#define RB       256              // row bytes (e4m3)
#define TM       256              // CTA tile rows (i)
#define TN       128              // CTA tile cols (j)
#define NIB      (NROWS / TM)     // 32
#define NJT      (NROWS / TN)     // 64
#define TT_TOTAL (NIB * NJT)      // 2048
#define GRID     148
#define ABYTES   (TM * RB)        // 65536
#define BBYTES   (TN * RB)        // 32768
#define SMEM_DYN (1024 + ABYTES + 2 * BBYTES)

__device__ __align__(16) uint8_t g_Zq[NROWS * RB];   // e4m3 normalized rows
__device__ float g_pos[NROWS];
__device__ float g_rowsum[NROWS];

// ---------------------------------------------------------------------------
__device__ __forceinline__ uint32_t smem_u32(const void* p) {
    uint32_t a;
    asm("{ .reg .u64 t; cvta.to.shared.u64 t, %1; cvt.u32.u64 %0, t; }" : "=r"(a) : "l"(p));
    return a;
}
__device__ __forceinline__ float ex2(float x) {
    float y; asm("ex2.approx.f32 %0, %1;" : "=f"(y) : "f"(x)); return y;
}
__device__ __forceinline__ void cpa16(uint32_t dst, const void* src) {
    asm volatile("cp.async.cg.shared.global [%0], [%1], 16;" :: "r"(dst), "l"(src) : "memory");
}
#define CP_COMMIT() asm volatile("cp.async.commit_group;" ::: "memory")
#define CP_WAIT0()  asm volatile("cp.async.wait_group 0;" ::: "memory")

#define LDSM_X4(R, ADDR)                                                         \
    asm volatile("ldmatrix.sync.aligned.m8n8.x4.shared.b16 {%0,%1,%2,%3}, [%4];" \
                 : "=r"((R)[0]), "=r"((R)[1]), "=r"((R)[2]), "=r"((R)[3])        \
                 : "r"(ADDR))

__device__ __forceinline__ void mma_e4m3(float* c, const uint32_t* a, uint32_t b0, uint32_t b1) {
    asm volatile(
        "mma.sync.aligned.m16n8k32.row.col.f32.e4m3.e4m3.f32 "
        "{%0,%1,%2,%3}, {%4,%5,%6,%7}, {%8,%9}, {%0,%1,%2,%3};"
        : "+f"(c[0]), "+f"(c[1]), "+f"(c[2]), "+f"(c[3])
        : "r"(a[0]), "r"(a[1]), "r"(a[2]), "r"(a[3]), "r"(b0), "r"(b1));
}

// SW128-style swizzled tile addressing. Atom = 8 rows x 128B.
// A tile: 256 rows (32 atom-rows); B tile: 128 rows (16 atom-rows).
__device__ __forceinline__ uint32_t taddrA(int r, int b) {
    uint32_t off = ((uint32_t)(r >> 3) + ((uint32_t)(b >> 7) << 5)) * 1024u
                 + (uint32_t)(r & 7) * 128u + (uint32_t)(b & 127);
    return off ^ ((off >> 3) & 0x70);
}
__device__ __forceinline__ uint32_t taddrB(int r, int b) {
    uint32_t off = ((uint32_t)(r >> 3) + ((uint32_t)(b >> 7) << 4)) * 1024u
                 + (uint32_t)(r & 7) * 128u + (uint32_t)(b & 127);
    return off ^ ((off >> 3) & 0x70);
}

// B tile: 128 rows x 256B = 2048 x 16B chunks; 512 threads -> 4 each.
__device__ __forceinline__ void loadB(uint32_t sdst, int row0, int tid) {
    #pragma unroll
    for (int it = 0; it < 4; ++it) {
        int idx = tid + it * 512;
        int r = idx >> 4, g = idx & 15;
        cpa16(sdst + taddrB(r, g * 16), g_Zq + (size_t)(row0 + r) * RB + g * 16);
    }
}
// A tile: 256 rows -> 4096 chunks; 8 per thread.
__device__ __forceinline__ void loadA(uint32_t sdst, int row0, int tid) {
    #pragma unroll
    for (int it = 0; it < 8; ++it) {
        int idx = tid + it * 512;
        int r = idx >> 4, g = idx & 15;
        cpa16(sdst + taddrA(r, g * 16), g_Zq + (size_t)(row0 + r) * RB + g * 16);
    }
}

// ---------------------------------------------------------------------------
// prep: one warp per pair. fp32 normalize, exact fp32 log(pos), e4m3 quantize.
// ---------------------------------------------------------------------------
__device__ __forceinline__ uint32_t pack4_e4m3(float f0, float f1, float f2, float f3) {
    uint16_t lo, hi;
    asm("cvt.rn.satfinite.e4m3x2.f32 %0, %1, %2;" : "=h"(lo) : "f"(f1), "f"(f0));
    asm("cvt.rn.satfinite.e4m3x2.f32 %0, %1, %2;" : "=h"(hi) : "f"(f3), "f"(f2));
    return (uint32_t)lo | ((uint32_t)hi << 16);
}

__global__ void __launch_bounds__(256) prep_kernel(const float* __restrict__ z1,
                                                   const float* __restrict__ z2) {
    const int p    = blockIdx.x * 8 + (threadIdx.x >> 5);
    const int lane = threadIdx.x & 31;
    const float4* p1 = reinterpret_cast<const float4*>(z1 + (size_t)p * D) + lane * 2;
    const float4* p2 = reinterpret_cast<const float4*>(z2 + (size_t)p * D) + lane * 2;
    float4 a0 = p1[0], a1 = p1[1];
    float4 b0 = p2[0], b1 = p2[1];
    float s1 = a0.x*a0.x + a0.y*a0.y + a0.z*a0.z + a0.w*a0.w
             + a1.x*a1.x + a1.y*a1.y + a1.z*a1.z + a1.w*a1.w;
    float s2 = b0.x*b0.x + b0.y*b0.y + b0.z*b0.z + b0.w*b0.w
             + b1.x*b1.x + b1.y*b1.y + b1.z*b1.z + b1.w*b1.w;
    float s3 = a0.x*b0.x + a0.y*b0.y + a0.z*b0.z + a0.w*b0.w
             + a1.x*b1.x + a1.y*b1.y + a1.z*b1.z + a1.w*b1.w;
    #pragma unroll
    for (int off = 16; off; off >>= 1) {
        s1 += __shfl_xor_sync(0xffffffffu, s1, off);
        s2 += __shfl_xor_sync(0xffffffffu, s2, off);
        s3 += __shfl_xor_sync(0xffffffffu, s3, off);
    }
    float inv1 = 1.0f / fmaxf(sqrtf(s1), 1e-12f);
    float inv2 = 1.0f / fmaxf(sqrtf(s2), 1e-12f);
    if (lane == 0) {
        float lp = 2.0f * (s3 * inv1 * inv2);
        g_pos[2*p] = lp; g_pos[2*p+1] = lp;
        g_rowsum[2*p] = 0.0f; g_rowsum[2*p+1] = 0.0f;
    }
    uint2 qa, qb;
    qa.x = pack4_e4m3(a0.x*inv1, a0.y*inv1, a0.z*inv1, a0.w*inv1);
    qa.y = pack4_e4m3(a1.x*inv1, a1.y*inv1, a1.z*inv1, a1.w*inv1);
    qb.x = pack4_e4m3(b0.x*inv2, b0.y*inv2, b0.z*inv2, b0.w*inv2);
    qb.y = pack4_e4m3(b1.x*inv2, b1.y*inv2, b1.z*inv2, b1.w*inv2);
    *reinterpret_cast<uint2*>(g_Zq + (size_t)(2*p)   * RB + lane * 8) = qa;
    *reinterpret_cast<uint2*>(g_Zq + (size_t)(2*p+1) * RB + lane * 8) = qb;
}

// ---------------------------------------------------------------------------
// Persistent fp8 GEMM + exp + row reduce.
// CTA: 256(i) x 128(j) tiles, K=256. 16 warps, warp tile 64x32 (grid 4m x 4n).
// ---------------------------------------------------------------------------
extern __shared__ char smem_raw[];

__device__ __forceinline__ void flush_acc(float* acc, int rowbase, int lane) {
    #pragma unroll
    for (int m = 0; m < 8; ++m) {
        float v = acc[m];
        v += __shfl_xor_sync(0xffffffffu, v, 1);
        v += __shfl_xor_sync(0xffffffffu, v, 2);
        if ((lane & 3) == 0)
            atomicAdd(&g_rowsum[rowbase + (m >> 1) * 16 + (m & 1) * 8 + (lane >> 2)], v);
        acc[m] = 0.0f;
    }
}

__global__ void __launch_bounds__(512, 1) gemm_kernel() {
    const uint32_t base = smem_u32(smem_raw);
    const uint32_t sb   = (base + 1023u) & ~1023u;
    const uint32_t sA   = sb;
    const uint32_t sB0  = sA + ABYTES;
    const uint32_t sB1  = sB0 + BBYTES;

    const int tid   = threadIdx.x;
    const int lane  = tid & 31;
    const int wid   = tid >> 5;
    const int warpM = wid & 3;        // 0..3 -> 64-row stripe
    const int warpN = wid >> 2;       // 0..3 -> 32-col stripe

    // Per-lane ldmatrix base addresses (ks = 0).
    uint32_t aAddr[4];
    {
        int rr  = warpM * 64 + (lane & 15);
        int sub = (lane >> 4) * 16;
        #pragma unroll
        for (int ma = 0; ma < 4; ++ma) aAddr[ma] = sA + taddrA(rr + ma * 16, sub);
    }
    uint32_t bOff[2];
    {
        int jo  = (lane & 7) + ((lane >> 4) << 3);
        int sub = ((lane >> 3) & 1) * 16;
        #pragma unroll
        for (int nb = 0; nb < 2; ++nb) bOff[nb] = taddrB(warpN * 32 + nb * 16 + jo, sub);
    }

    const int beg = (blockIdx.x * TT_TOTAL) / GRID;
    const int end = ((blockIdx.x + 1) * TT_TOTAL) / GRID;
    int cur_ib = beg / NJT;

    loadA(sA, cur_ib * TM, tid);
    CP_COMMIT();
    loadB(sB0, (beg % NJT) * TN, tid);
    CP_COMMIT();
    CP_WAIT0();
    __syncthreads();

    float acc[8] = {0.f, 0.f, 0.f, 0.f, 0.f, 0.f, 0.f, 0.f};
    const float C = 2.8853900817779268f;   // 2 / ln2

    for (int t = beg; t < end; ++t) {
        const int buf = (t - beg) & 1;
        if (t + 1 < end) {                         // prefetch next B into other buffer
            loadB(buf ? sB0 : sB1, ((t + 1) % NJT) * TN, tid);
            CP_COMMIT();
        }

        // ---- compute tile on buffer `buf` ----
        const uint32_t bb = buf ? sB1 : sB0;
        float c[4][4][4];
        #pragma unroll
        for (int ma = 0; ma < 4; ++ma)
            #pragma unroll
            for (int na = 0; na < 4; ++na)
                #pragma unroll
                for (int q = 0; q < 4; ++q) c[ma][na][q] = 0.0f;

        #pragma unroll
        for (int ks = 0; ks < 8; ++ks) {
            const uint32_t koA = (uint32_t)((ks & 3) * 32 + (ks >> 2) * 32768);
            const uint32_t koB = (uint32_t)((ks & 3) * 32 + (ks >> 2) * 16384);
            uint32_t a[4][4];
            #pragma unroll
            for (int ma = 0; ma < 4; ++ma) LDSM_X4(a[ma], aAddr[ma] + koA);
            uint32_t b[2][4];
            #pragma unroll
            for (int nb = 0; nb < 2; ++nb) LDSM_X4(b[nb], bb + bOff[nb] + koB);
            #pragma unroll
            for (int ma = 0; ma < 4; ++ma) {
                #pragma unroll
                for (int nb = 0; nb < 2; ++nb) {
                    mma_e4m3(c[ma][nb * 2 + 0], a[ma], b[nb][0], b[nb][1]);
                    mma_e4m3(c[ma][nb * 2 + 1], a[ma], b[nb][2], b[nb][3]);
                }
            }
        }

        // ---- epilogue: exp(2*dot) accumulate into per-row acc ----
        #pragma unroll
        for (int ma = 0; ma < 4; ++ma) {
            float s0 = 0.f, s1 = 0.f;
            #pragma unroll
            for (int na = 0; na < 4; ++na) {
                s0 += ex2(c[ma][na][0] * C) + ex2(c[ma][na][1] * C);
                s1 += ex2(c[ma][na][2] * C) + ex2(c[ma][na][3] * C);
            }
            acc[ma * 2 + 0] += s0;
            acc[ma * 2 + 1] += s1;
        }

        // ---- A-tile change handling ----
        if (t + 1 < end) {
            const int nib = (t + 1) / NJT;
            if (nib != cur_ib) {
                flush_acc(acc, cur_ib * TM + warpM * 64, lane);
                __syncthreads();            // everyone done reading sA
                loadA(sA, nib * TM, tid);
                CP_COMMIT();
                cur_ib = nib;
            }
        }
        CP_WAIT0();          // next B (and A if reloaded) complete
        __syncthreads();
    }

    flush_acc(acc, cur_ib * TM + warpM * 64, lane);
}

// ---------------------------------------------------------------------------
__global__ void loss_kernel(float* __restrict__ out) {
    const float E2 = 7.3890560989306495f;
    float acc = 0.0f;
    for (int i = threadIdx.x; i < NROWS; i += 256)
        acc += logf(g_rowsum[i] - E2 + 1e-8f) - g_pos[i];
    #pragma unroll
    for (int off = 16; off; off >>= 1)
        acc += __shfl_xor_sync(0xffffffffu, acc, off);
    __shared__ float sh[8];
    if ((threadIdx.x & 31) == 0) sh[threadIdx.x >> 5] = acc;
    __syncthreads();
    if (threadIdx.x == 0) {
        float t = 0.f;
        #pragma unroll
        for (int i = 0; i < 8; ++i) t += sh[i];
        out[0] = t * (1.0f / (float)NROWS);
    }
}

// ---------------------------------------------------------------------------
extern "C" void kernel_launch(void* const* d_in, const int* in_sizes, int n_in,
                              void* d_out, int out_size) {
    const float* z1 = (const float*)d_in[0];
    const float* z2 = (const float*)d_in[1];
    float* out = (float*)d_out;

    prep_kernel<<<NROWS / 2 / 8, 256>>>(z1, z2);

    cudaFuncSetAttribute(gemm_kernel, cudaFuncAttributeMaxDynamicSharedMemorySize, SMEM_DYN);
    gemm_kernel<<<GRID, 512, SMEM_DYN>>>();

    loss_kernel<<<1, 256>>>(out);
}

// round 5
// speedup vs baseline: 1.8504x; 1.4901x over previous
#include <cuda_runtime.h>
#include <cuda_bf16.h>
#include <cstdint>

// z1, z2: (4096, 256) fp32. Interleaved normalized Z: (8192, 256), quantized e4m3.
// loss = mean_i [ log(sum_j exp(2 z_i.z_j) - e^2 + 1e-8) - 2 z_i.z_{i^1} ]
// Symmetric: tile (IB, jb) computed only for jb >= 2*IB (A block = 256 rows,
// B block = 128 cols). Transpose term added via column sums, per 128-row half,
// iff 2*IB + half < (jb & ~1)  -> every S block counted exactly once.
#define D        256
#define NROWS    8192
#define RB       256              // row bytes (e4m3)
#define TM       256              // CTA tile rows (i)
#define TN       128              // CTA tile cols (j)
#define NJB      (NROWS / TN)     // 64
#define NTASK    1056             // sum_{IB=0}^{31} (64 - 2*IB)
#define GRID     148
#define ABYTES   (TM * RB)        // 65536
#define BBYTES   (TN * RB)        // 32768
#define SMEM_DYN (1024 + ABYTES + 2 * BBYTES)

__device__ __align__(16) uint8_t g_Zq[NROWS * RB];   // e4m3 normalized rows
__device__ float g_pos[NROWS];
__device__ float g_rowsum[NROWS];

// ---------------------------------------------------------------------------
__device__ __forceinline__ uint32_t smem_u32(const void* p) {
    uint32_t a;
    asm("{ .reg .u64 t; cvta.to.shared.u64 t, %1; cvt.u32.u64 %0, t; }" : "=r"(a) : "l"(p));
    return a;
}
__device__ __forceinline__ float ex2(float x) {
    float y; asm("ex2.approx.f32 %0, %1;" : "=f"(y) : "f"(x)); return y;
}
__device__ __forceinline__ void cpa16(uint32_t dst, const void* src) {
    asm volatile("cp.async.cg.shared.global [%0], [%1], 16;" :: "r"(dst), "l"(src) : "memory");
}
#define CP_COMMIT() asm volatile("cp.async.commit_group;" ::: "memory")
#define CP_WAIT0()  asm volatile("cp.async.wait_group 0;" ::: "memory")

#define LDSM_X4(R, ADDR)                                                         \
    asm volatile("ldmatrix.sync.aligned.m8n8.x4.shared.b16 {%0,%1,%2,%3}, [%4];" \
                 : "=r"((R)[0]), "=r"((R)[1]), "=r"((R)[2]), "=r"((R)[3])        \
                 : "r"(ADDR))

__device__ __forceinline__ void mma_e4m3(float* c, const uint32_t* a, uint32_t b0, uint32_t b1) {
    asm volatile(
        "mma.sync.aligned.m16n8k32.row.col.f32.e4m3.e4m3.f32 "
        "{%0,%1,%2,%3}, {%4,%5,%6,%7}, {%8,%9}, {%0,%1,%2,%3};"
        : "+f"(c[0]), "+f"(c[1]), "+f"(c[2]), "+f"(c[3])
        : "r"(a[0]), "r"(a[1]), "r"(a[2]), "r"(a[3]), "r"(b0), "r"(b1));
}

// SW128-style swizzled tile addressing. Atom = 8 rows x 128B.
// A tile: 256 rows (32 atom-rows); B tile: 128 rows (16 atom-rows).
__device__ __forceinline__ uint32_t taddrA(int r, int b) {
    uint32_t off = ((uint32_t)(r >> 3) + ((uint32_t)(b >> 7) << 5)) * 1024u
                 + (uint32_t)(r & 7) * 128u + (uint32_t)(b & 127);
    return off ^ ((off >> 3) & 0x70);
}
__device__ __forceinline__ uint32_t taddrB(int r, int b) {
    uint32_t off = ((uint32_t)(r >> 3) + ((uint32_t)(b >> 7) << 4)) * 1024u
                 + (uint32_t)(r & 7) * 128u + (uint32_t)(b & 127);
    return off ^ ((off >> 3) & 0x70);
}

// B tile: 128 rows x 256B = 2048 x 16B chunks; 512 threads -> 4 each.
__device__ __forceinline__ void loadB(uint32_t sdst, int row0, int tid) {
    #pragma unroll
    for (int it = 0; it < 4; ++it) {
        int idx = tid + it * 512;
        int r = idx >> 4, g = idx & 15;
        cpa16(sdst + taddrB(r, g * 16), g_Zq + (size_t)(row0 + r) * RB + g * 16);
    }
}
// A tile: 256 rows -> 4096 chunks; 8 per thread.
__device__ __forceinline__ void loadA(uint32_t sdst, int row0, int tid) {
    #pragma unroll
    for (int it = 0; it < 8; ++it) {
        int idx = tid + it * 512;
        int r = idx >> 4, g = idx & 15;
        cpa16(sdst + taddrA(r, g * 16), g_Zq + (size_t)(row0 + r) * RB + g * 16);
    }
}

// ---------------------------------------------------------------------------
// prep: one warp per pair. fp32 normalize, exact fp32 log(pos), e4m3 quantize.
// ---------------------------------------------------------------------------
__device__ __forceinline__ uint32_t pack4_e4m3(float f0, float f1, float f2, float f3) {
    uint16_t lo, hi;
    asm("cvt.rn.satfinite.e4m3x2.f32 %0, %1, %2;" : "=h"(lo) : "f"(f1), "f"(f0));
    asm("cvt.rn.satfinite.e4m3x2.f32 %0, %1, %2;" : "=h"(hi) : "f"(f3), "f"(f2));
    return (uint32_t)lo | ((uint32_t)hi << 16);
}

__global__ void __launch_bounds__(256) prep_kernel(const float* __restrict__ z1,
                                                   const float* __restrict__ z2) {
    const int p    = blockIdx.x * 8 + (threadIdx.x >> 5);
    const int lane = threadIdx.x & 31;
    const float4* p1 = reinterpret_cast<const float4*>(z1 + (size_t)p * D) + lane * 2;
    const float4* p2 = reinterpret_cast<const float4*>(z2 + (size_t)p * D) + lane * 2;
    float4 a0 = p1[0], a1 = p1[1];
    float4 b0 = p2[0], b1 = p2[1];
    float s1 = a0.x*a0.x + a0.y*a0.y + a0.z*a0.z + a0.w*a0.w
             + a1.x*a1.x + a1.y*a1.y + a1.z*a1.z + a1.w*a1.w;
    float s2 = b0.x*b0.x + b0.y*b0.y + b0.z*b0.z + b0.w*b0.w
             + b1.x*b1.x + b1.y*b1.y + b1.z*b1.z + b1.w*b1.w;
    float s3 = a0.x*b0.x + a0.y*b0.y + a0.z*b0.z + a0.w*b0.w
             + a1.x*b1.x + a1.y*b1.y + a1.z*b1.z + a1.w*b1.w;
    #pragma unroll
    for (int off = 16; off; off >>= 1) {
        s1 += __shfl_xor_sync(0xffffffffu, s1, off);
        s2 += __shfl_xor_sync(0xffffffffu, s2, off);
        s3 += __shfl_xor_sync(0xffffffffu, s3, off);
    }
    float inv1 = 1.0f / fmaxf(sqrtf(s1), 1e-12f);
    float inv2 = 1.0f / fmaxf(sqrtf(s2), 1e-12f);
    if (lane == 0) {
        float lp = 2.0f * (s3 * inv1 * inv2);
        g_pos[2*p] = lp; g_pos[2*p+1] = lp;
        g_rowsum[2*p] = 0.0f; g_rowsum[2*p+1] = 0.0f;
    }
    uint2 qa, qb;
    qa.x = pack4_e4m3(a0.x*inv1, a0.y*inv1, a0.z*inv1, a0.w*inv1);
    qa.y = pack4_e4m3(a1.x*inv1, a1.y*inv1, a1.z*inv1, a1.w*inv1);
    qb.x = pack4_e4m3(b0.x*inv2, b0.y*inv2, b0.z*inv2, b0.w*inv2);
    qb.y = pack4_e4m3(b1.x*inv2, b1.y*inv2, b1.z*inv2, b1.w*inv2);
    *reinterpret_cast<uint2*>(g_Zq + (size_t)(2*p)   * RB + lane * 8) = qa;
    *reinterpret_cast<uint2*>(g_Zq + (size_t)(2*p+1) * RB + lane * 8) = qb;
}

// ---------------------------------------------------------------------------
// Persistent symmetric fp8 GEMM + exp + row/col reduce.
// CTA: 256(i) x 128(j) tiles, K=256. 16 warps, warp tile 64x32 (grid 4m x 4n).
// Task (IB, jb) computed iff jb >= 2*IB.
// ---------------------------------------------------------------------------
extern __shared__ char smem_raw[];

__device__ __forceinline__ void flush_acc(float* acc, int rowbase, int lane) {
    #pragma unroll
    for (int m = 0; m < 8; ++m) {
        float v = acc[m];
        v += __shfl_xor_sync(0xffffffffu, v, 1);
        v += __shfl_xor_sync(0xffffffffu, v, 2);
        if ((lane & 3) == 0)
            atomicAdd(&g_rowsum[rowbase + (m >> 1) * 16 + (m & 1) * 8 + (lane >> 2)], v);
        acc[m] = 0.0f;
    }
}

__global__ void __launch_bounds__(512, 1) gemm_kernel() {
    const uint32_t base = smem_u32(smem_raw);
    const uint32_t sb   = (base + 1023u) & ~1023u;
    const uint32_t sA   = sb;
    const uint32_t sB0  = sA + ABYTES;
    const uint32_t sB1  = sB0 + BBYTES;

    const int tid   = threadIdx.x;
    const int lane  = tid & 31;
    const int wid   = tid >> 5;
    const int warpM = wid & 3;        // 0..3 -> 64-row stripe
    const int warpN = wid >> 2;       // 0..3 -> 32-col stripe
    const int half  = warpM >> 1;     // 0: rows [0,128) = block 2*IB, 1: block 2*IB+1

    uint32_t aAddr[4];
    {
        int rr  = warpM * 64 + (lane & 15);
        int sub = (lane >> 4) * 16;
        #pragma unroll
        for (int ma = 0; ma < 4; ++ma) aAddr[ma] = sA + taddrA(rr + ma * 16, sub);
    }
    uint32_t bOff[2];
    {
        int jo  = (lane & 7) + ((lane >> 4) << 3);
        int sub = ((lane >> 3) & 1) * 16;
        #pragma unroll
        for (int nb = 0; nb < 2; ++nb) bOff[nb] = taddrB(warpN * 32 + nb * 16 + jo, sub);
    }

    const int beg = (blockIdx.x * NTASK) / GRID;
    const int end = ((blockIdx.x + 1) * NTASK) / GRID;

    // decode beg -> (IB, jb): row IB has (64 - 2*IB) tasks, jb from 2*IB to 63
    int IB = 0, rem = beg;
    while (rem >= NJB - 2 * IB) { rem -= NJB - 2 * IB; ++IB; }
    int jb = 2 * IB + rem;

    loadA(sA, IB * TM, tid);  CP_COMMIT();
    loadB(sB0, jb * TN, tid); CP_COMMIT();
    CP_WAIT0();
    __syncthreads();

    float acc[8] = {0.f, 0.f, 0.f, 0.f, 0.f, 0.f, 0.f, 0.f};
    const float C = 2.8853900817779268f;   // 2 / ln2

    for (int t = beg; t < end; ++t) {
        const int buf = (t - beg) & 1;
        int IBn = IB, jbn = jb + 1;
        if (jbn == NJB) { IBn = IB + 1; jbn = 2 * IBn; }
        const bool more = (t + 1 < end);
        if (more) { loadB(buf ? sB0 : sB1, jbn * TN, tid); CP_COMMIT(); }

        // ---- compute tile on buffer `buf` ----
        const uint32_t bb = buf ? sB1 : sB0;
        float c[4][4][4];
        #pragma unroll
        for (int ma = 0; ma < 4; ++ma)
            #pragma unroll
            for (int na = 0; na < 4; ++na)
                #pragma unroll
                for (int q = 0; q < 4; ++q) c[ma][na][q] = 0.0f;

        #pragma unroll
        for (int ks = 0; ks < 8; ++ks) {
            const uint32_t koA = (uint32_t)((ks & 3) * 32 + (ks >> 2) * 32768);
            const uint32_t koB = (uint32_t)((ks & 3) * 32 + (ks >> 2) * 16384);
            uint32_t a[4][4];
            #pragma unroll
            for (int ma = 0; ma < 4; ++ma) LDSM_X4(a[ma], aAddr[ma] + koA);
            uint32_t b[2][4];
            #pragma unroll
            for (int nb = 0; nb < 2; ++nb) LDSM_X4(b[nb], bb + bOff[nb] + koB);
            #pragma unroll
            for (int ma = 0; ma < 4; ++ma) {
                #pragma unroll
                for (int nb = 0; nb < 2; ++nb) {
                    mma_e4m3(c[ma][nb * 2 + 0], a[ma], b[nb][0], b[nb][1]);
                    mma_e4m3(c[ma][nb * 2 + 1], a[ma], b[nb][2], b[nb][3]);
                }
            }
        }

        // ---- epilogue: E = exp(2*dot); rows always; cols iff transpose needed ----
        // This warp's 64 rows lie in 128-block (2*IB + half). Transpose pair
        // (jb, 2*IB+half) is NOT computed directly iff 2*IB+half < (jb & ~1).
        const bool doCols = (2 * IB + half) < (jb & ~1);
        float cs[4][2] = {{0.f,0.f},{0.f,0.f},{0.f,0.f},{0.f,0.f}};
        #pragma unroll
        for (int ma = 0; ma < 4; ++ma) {
            #pragma unroll
            for (int na = 0; na < 4; ++na) {
                float e0 = ex2(c[ma][na][0] * C);
                float e1 = ex2(c[ma][na][1] * C);
                float e2 = ex2(c[ma][na][2] * C);
                float e3 = ex2(c[ma][na][3] * C);
                acc[ma * 2 + 0] += e0 + e1;      // row g
                acc[ma * 2 + 1] += e2 + e3;      // row g+8
                if (doCols) {
                    cs[na][0] += e0 + e2;        // col 2t
                    cs[na][1] += e1 + e3;        // col 2t+1
                }
            }
        }
        if (doCols) {
            #pragma unroll
            for (int na = 0; na < 4; ++na) {
                float v0 = cs[na][0], v1 = cs[na][1];
                #pragma unroll
                for (int off = 4; off < 32; off <<= 1) {
                    v0 += __shfl_xor_sync(0xffffffffu, v0, off);
                    v1 += __shfl_xor_sync(0xffffffffu, v1, off);
                }
                if (lane < 4) {
                    int j = jb * TN + warpN * 32 + na * 8 + 2 * lane;
                    atomicAdd(&g_rowsum[j],     v0);
                    atomicAdd(&g_rowsum[j + 1], v1);
                }
            }
        }

        // ---- A-tile change ----
        if (more && IBn != IB) {
            flush_acc(acc, IB * TM + warpM * 64, lane);
            __syncthreads();                 // all warps done reading sA
            loadA(sA, IBn * TM, tid);
            CP_COMMIT();
        }
        if (more) { IB = IBn; jb = jbn; }
        CP_WAIT0();
        __syncthreads();
    }

    flush_acc(acc, IB * TM + warpM * 64, lane);
}

// ---------------------------------------------------------------------------
__global__ void loss_kernel(float* __restrict__ out) {
    const float E2 = 7.3890560989306495f;
    float acc = 0.0f;
    for (int i = threadIdx.x; i < NROWS; i += 256)
        acc += logf(g_rowsum[i] - E2 + 1e-8f) - g_pos[i];
    #pragma unroll
    for (int off = 16; off; off >>= 1)
        acc += __shfl_xor_sync(0xffffffffu, acc, off);
    __shared__ float sh[8];
    if ((threadIdx.x & 31) == 0) sh[threadIdx.x >> 5] = acc;
    __syncthreads();
    if (threadIdx.x == 0) {
        float t = 0.f;
        #pragma unroll
        for (int i = 0; i < 8; ++i) t += sh[i];
        out[0] = t * (1.0f / (float)NROWS);
    }
}

// ---------------------------------------------------------------------------
extern "C" void kernel_launch(void* const* d_in, const int* in_sizes, int n_in,
                              void* d_out, int out_size) {
    const float* z1 = (const float*)d_in[0];
    const float* z2 = (const float*)d_in[1];
    float* out = (float*)d_out;

    prep_kernel<<<NROWS / 2 / 8, 256>>>(z1, z2);

    cudaFuncSetAttribute(gemm_kernel, cudaFuncAttributeMaxDynamicSharedMemorySize, SMEM_DYN);
    gemm_kernel<<<GRID, 512, SMEM_DYN>>>();

    loss_kernel<<<1, 256>>>(out);
}

// round 6
// speedup vs baseline: 1.8617x; 1.0061x over previous
#include <cuda_runtime.h>
#include <cuda_bf16.h>
#include <cstdint>

// z1, z2: (4096, 256) fp32. Interleaved normalized Z: (8192, 256), quantized e4m3
// with the exp scale folded in: q = sqrt(2/ln2) * z_hat, so dot_q = (2/ln2) * dot.
// loss = mean_i [ log(sum_j exp(2 z_i.z_j) - e^2 + 1e-8) - 2 z_i.z_{i^1} ]
// Symmetric: tile (IB, jb) computed only for jb >= 2*IB (A block = 256 rows,
// B block = 128 cols). Transpose term added via column sums, per 128-row half,
// iff 2*IB + half < (jb & ~1)  -> every S block counted exactly once.
#define D        256
#define NROWS    8192
#define RB       256              // row bytes (e4m3)
#define TM       256              // CTA tile rows (i)
#define TN       128              // CTA tile cols (j)
#define NJB      (NROWS / TN)     // 64
#define NTASK    1056             // sum_{IB=0}^{31} (64 - 2*IB)
#define GRID     148
#define ABYTES   (TM * RB)        // 65536
#define BBYTES   (TN * RB)        // 32768
#define SMEM_DYN (1024 + ABYTES + 2 * BBYTES)

#define QSCALE   1.6986436f       // sqrt(2 / ln 2)

__device__ __align__(16) uint8_t g_Zq[NROWS * RB];   // e4m3 scaled normalized rows
__device__ float g_pos[NROWS];
__device__ float g_rowsum[NROWS];

// ---------------------------------------------------------------------------
__device__ __forceinline__ uint32_t smem_u32(const void* p) {
    uint32_t a;
    asm("{ .reg .u64 t; cvta.to.shared.u64 t, %1; cvt.u32.u64 %0, t; }" : "=r"(a) : "l"(p));
    return a;
}
__device__ __forceinline__ float ex2(float x) {
    float y; asm("ex2.approx.f32 %0, %1;" : "=f"(y) : "f"(x)); return y;
}
__device__ __forceinline__ void cpa16(uint32_t dst, const void* src) {
    asm volatile("cp.async.cg.shared.global [%0], [%1], 16;" :: "r"(dst), "l"(src) : "memory");
}
#define CP_COMMIT() asm volatile("cp.async.commit_group;" ::: "memory")
#define CP_WAIT0()  asm volatile("cp.async.wait_group 0;" ::: "memory")

#define LDSM_X4(R, ADDR)                                                         \
    asm volatile("ldmatrix.sync.aligned.m8n8.x4.shared.b16 {%0,%1,%2,%3}, [%4];" \
                 : "=r"((R)[0]), "=r"((R)[1]), "=r"((R)[2]), "=r"((R)[3])        \
                 : "r"(ADDR))

__device__ __forceinline__ void mma_e4m3(float* c, const uint32_t* a, uint32_t b0, uint32_t b1) {
    asm volatile(
        "mma.sync.aligned.m16n8k32.row.col.f32.e4m3.e4m3.f32 "
        "{%0,%1,%2,%3}, {%4,%5,%6,%7}, {%8,%9}, {%0,%1,%2,%3};"
        : "+f"(c[0]), "+f"(c[1]), "+f"(c[2]), "+f"(c[3])
        : "r"(a[0]), "r"(a[1]), "r"(a[2]), "r"(a[3]), "r"(b0), "r"(b1));
}

// SW128-style swizzled tile addressing. Atom = 8 rows x 128B.
// A tile: 256 rows (32 atom-rows); B tile: 128 rows (16 atom-rows).
__device__ __forceinline__ uint32_t taddrA(int r, int b) {
    uint32_t off = ((uint32_t)(r >> 3) + ((uint32_t)(b >> 7) << 5)) * 1024u
                 + (uint32_t)(r & 7) * 128u + (uint32_t)(b & 127);
    return off ^ ((off >> 3) & 0x70);
}
__device__ __forceinline__ uint32_t taddrB(int r, int b) {
    uint32_t off = ((uint32_t)(r >> 3) + ((uint32_t)(b >> 7) << 4)) * 1024u
                 + (uint32_t)(r & 7) * 128u + (uint32_t)(b & 127);
    return off ^ ((off >> 3) & 0x70);
}

// B tile: 128 rows x 256B = 2048 x 16B chunks; 512 threads -> 4 each.
__device__ __forceinline__ void loadB(uint32_t sdst, int row0, int tid) {
    #pragma unroll
    for (int it = 0; it < 4; ++it) {
        int idx = tid + it * 512;
        int r = idx >> 4, g = idx & 15;
        cpa16(sdst + taddrB(r, g * 16), g_Zq + (size_t)(row0 + r) * RB + g * 16);
    }
}
// A tile: 256 rows -> 4096 chunks; 8 per thread.
__device__ __forceinline__ void loadA(uint32_t sdst, int row0, int tid) {
    #pragma unroll
    for (int it = 0; it < 8; ++it) {
        int idx = tid + it * 512;
        int r = idx >> 4, g = idx & 15;
        cpa16(sdst + taddrA(r, g * 16), g_Zq + (size_t)(row0 + r) * RB + g * 16);
    }
}

// ---------------------------------------------------------------------------
// prep: 64 threads (2 warps) per pair -> 4 pairs per 256-thread block.
// fp32 normalize, exact fp32 log(pos), e4m3 quantize with QSCALE folded in.
// ---------------------------------------------------------------------------
__device__ __forceinline__ uint32_t pack4_e4m3(float f0, float f1, float f2, float f3) {
    uint16_t lo, hi;
    asm("cvt.rn.satfinite.e4m3x2.f32 %0, %1, %2;" : "=h"(lo) : "f"(f1), "f"(f0));
    asm("cvt.rn.satfinite.e4m3x2.f32 %0, %1, %2;" : "=h"(hi) : "f"(f3), "f"(f2));
    return (uint32_t)lo | ((uint32_t)hi << 16);
}

__global__ void __launch_bounds__(256) prep_kernel(const float* __restrict__ z1,
                                                   const float* __restrict__ z2) {
    const int tid  = threadIdx.x;
    const int lane = tid & 31;
    const int w    = tid >> 5;          // warp 0..7
    const int sub  = tid & 63;          // thread within pair-group
    const int p    = blockIdx.x * 4 + (tid >> 6);   // pair 0..4095

    const float4 a = reinterpret_cast<const float4*>(z1 + (size_t)p * D)[sub];
    const float4 b = reinterpret_cast<const float4*>(z2 + (size_t)p * D)[sub];
    float s1 = a.x*a.x + a.y*a.y + a.z*a.z + a.w*a.w;
    float s2 = b.x*b.x + b.y*b.y + b.z*b.z + b.w*b.w;
    float s3 = a.x*b.x + a.y*b.y + a.z*b.z + a.w*b.w;
    #pragma unroll
    for (int off = 16; off; off >>= 1) {
        s1 += __shfl_xor_sync(0xffffffffu, s1, off);
        s2 += __shfl_xor_sync(0xffffffffu, s2, off);
        s3 += __shfl_xor_sync(0xffffffffu, s3, off);
    }
    __shared__ float sh[8][3];
    if (lane == 0) { sh[w][0] = s1; sh[w][1] = s2; sh[w][2] = s3; }
    __syncthreads();
    const int wo = w ^ 1;               // sibling warp of the same pair
    float t1 = sh[w][0] + sh[wo][0];
    float t2 = sh[w][1] + sh[wo][1];
    float t3 = sh[w][2] + sh[wo][2];

    float inv1 = 1.0f / fmaxf(sqrtf(t1), 1e-12f);
    float inv2 = 1.0f / fmaxf(sqrtf(t2), 1e-12f);
    if (sub == 0) {
        float lp = 2.0f * (t3 * inv1 * inv2);
        g_pos[2*p] = lp; g_pos[2*p+1] = lp;
        g_rowsum[2*p] = 0.0f; g_rowsum[2*p+1] = 0.0f;
    }
    const float q1 = inv1 * QSCALE, q2 = inv2 * QSCALE;
    *reinterpret_cast<uint32_t*>(g_Zq + (size_t)(2*p)   * RB + sub * 4) =
        pack4_e4m3(a.x*q1, a.y*q1, a.z*q1, a.w*q1);
    *reinterpret_cast<uint32_t*>(g_Zq + (size_t)(2*p+1) * RB + sub * 4) =
        pack4_e4m3(b.x*q2, b.y*q2, b.z*q2, b.w*q2);
}

// ---------------------------------------------------------------------------
// Persistent symmetric fp8 GEMM + exp + row/col reduce.
// CTA: 256(i) x 128(j) tiles, K=256. 16 warps, warp tile 64x32 (grid 4m x 4n).
// Task (IB, jb) computed iff jb >= 2*IB. k-loop software-pipelined.
// ---------------------------------------------------------------------------
extern __shared__ char smem_raw[];

__device__ __forceinline__ void flush_acc(float* acc, int rowbase, int lane) {
    #pragma unroll
    for (int m = 0; m < 8; ++m) {
        float v = acc[m];
        v += __shfl_xor_sync(0xffffffffu, v, 1);
        v += __shfl_xor_sync(0xffffffffu, v, 2);
        if ((lane & 3) == 0)
            atomicAdd(&g_rowsum[rowbase + (m >> 1) * 16 + (m & 1) * 8 + (lane >> 2)], v);
        acc[m] = 0.0f;
    }
}

__global__ void __launch_bounds__(512, 1) gemm_kernel() {
    const uint32_t base = smem_u32(smem_raw);
    const uint32_t sb   = (base + 1023u) & ~1023u;
    const uint32_t sA   = sb;
    const uint32_t sB0  = sA + ABYTES;
    const uint32_t sB1  = sB0 + BBYTES;

    const int tid   = threadIdx.x;
    const int lane  = tid & 31;
    const int wid   = tid >> 5;
    const int warpM = wid & 3;        // 0..3 -> 64-row stripe
    const int warpN = wid >> 2;       // 0..3 -> 32-col stripe
    const int half  = warpM >> 1;     // 0: rows in block 2*IB, 1: block 2*IB+1

    uint32_t aAddr[4];
    {
        int rr  = warpM * 64 + (lane & 15);
        int sub = (lane >> 4) * 16;
        #pragma unroll
        for (int ma = 0; ma < 4; ++ma) aAddr[ma] = sA + taddrA(rr + ma * 16, sub);
    }
    uint32_t bOff[2];
    {
        int jo  = (lane & 7) + ((lane >> 4) << 3);
        int sub = ((lane >> 3) & 1) * 16;
        #pragma unroll
        for (int nb = 0; nb < 2; ++nb) bOff[nb] = taddrB(warpN * 32 + nb * 16 + jo, sub);
    }

    const int beg = (blockIdx.x * NTASK) / GRID;
    const int end = ((blockIdx.x + 1) * NTASK) / GRID;

    // decode beg -> (IB, jb): row IB has (64 - 2*IB) tasks, jb from 2*IB to 63
    int IB = 0, rem = beg;
    while (rem >= NJB - 2 * IB) { rem -= NJB - 2 * IB; ++IB; }
    int jb = 2 * IB + rem;

    loadA(sA, IB * TM, tid);  CP_COMMIT();
    loadB(sB0, jb * TN, tid); CP_COMMIT();
    CP_WAIT0();
    __syncthreads();

    float acc[8] = {0.f, 0.f, 0.f, 0.f, 0.f, 0.f, 0.f, 0.f};

    for (int t = beg; t < end; ++t) {
        const int buf = (t - beg) & 1;
        int IBn = IB, jbn = jb + 1;
        if (jbn == NJB) { IBn = IB + 1; jbn = 2 * IBn; }
        const bool more = (t + 1 < end);
        if (more) { loadB(buf ? sB0 : sB1, jbn * TN, tid); CP_COMMIT(); }

        // ---- compute tile on buffer `buf` (software-pipelined k-loop) ----
        const uint32_t bb = buf ? sB1 : sB0;
        float c[4][4][4];
        #pragma unroll
        for (int ma = 0; ma < 4; ++ma)
            #pragma unroll
            for (int na = 0; na < 4; ++na)
                #pragma unroll
                for (int q = 0; q < 4; ++q) c[ma][na][q] = 0.0f;

        uint32_t a0[4][4], a1[4][4], b[2][4];
#define LOAD_A(dst, ks) do {                                                   \
        const uint32_t ko = (uint32_t)((((ks) & 3) * 32) + (((ks) >> 2) * 32768)); \
        LDSM_X4((dst)[0], aAddr[0] + ko); LDSM_X4((dst)[1], aAddr[1] + ko);    \
        LDSM_X4((dst)[2], aAddr[2] + ko); LDSM_X4((dst)[3], aAddr[3] + ko);    \
    } while (0)
#define LOAD_B(ks) do {                                                        \
        const uint32_t ko = (uint32_t)((((ks) & 3) * 32) + (((ks) >> 2) * 16384)); \
        LDSM_X4(b[0], bb + bOff[0] + ko); LDSM_X4(b[1], bb + bOff[1] + ko);    \
    } while (0)
#define MMAS(aa) do {                                                          \
        _Pragma("unroll")                                                      \
        for (int ma = 0; ma < 4; ++ma) {                                       \
            mma_e4m3(c[ma][0], (aa)[ma], b[0][0], b[0][1]);                    \
            mma_e4m3(c[ma][1], (aa)[ma], b[0][2], b[0][3]);                    \
            mma_e4m3(c[ma][2], (aa)[ma], b[1][0], b[1][1]);                    \
            mma_e4m3(c[ma][3], (aa)[ma], b[1][2], b[1][3]);                    \
        }                                                                      \
    } while (0)

        LOAD_A(a0, 0);
        LOAD_B(0);
        #pragma unroll
        for (int ks = 0; ks < 8; ks += 2) {
            LOAD_A(a1, ks + 1);
            MMAS(a0);                       // consumes b(ks)
            LOAD_B(ks + 1);
            if (ks < 6) LOAD_A(a0, ks + 2);
            MMAS(a1);                       // consumes b(ks+1)
            if (ks < 6) LOAD_B(ks + 2);
        }
#undef LOAD_A
#undef LOAD_B
#undef MMAS

        // ---- epilogue: E = 2^(c) (scale folded); rows always; cols iff needed ----
        const bool doCols = (2 * IB + half) < (jb & ~1);
        float cs[4][2] = {{0.f,0.f},{0.f,0.f},{0.f,0.f},{0.f,0.f}};
        #pragma unroll
        for (int ma = 0; ma < 4; ++ma) {
            #pragma unroll
            for (int na = 0; na < 4; ++na) {
                float e0 = ex2(c[ma][na][0]);
                float e1 = ex2(c[ma][na][1]);
                float e2 = ex2(c[ma][na][2]);
                float e3 = ex2(c[ma][na][3]);
                acc[ma * 2 + 0] += e0 + e1;      // row g
                acc[ma * 2 + 1] += e2 + e3;      // row g+8
                if (doCols) {
                    cs[na][0] += e0 + e2;        // col 2t
                    cs[na][1] += e1 + e3;        // col 2t+1
                }
            }
        }
        if (doCols) {
            #pragma unroll
            for (int na = 0; na < 4; ++na) {
                float v0 = cs[na][0], v1 = cs[na][1];
                #pragma unroll
                for (int off = 4; off < 32; off <<= 1) {
                    v0 += __shfl_xor_sync(0xffffffffu, v0, off);
                    v1 += __shfl_xor_sync(0xffffffffu, v1, off);
                }
                if (lane < 4) {
                    int j = jb * TN + warpN * 32 + na * 8 + 2 * lane;
                    atomicAdd(&g_rowsum[j],     v0);
                    atomicAdd(&g_rowsum[j + 1], v1);
                }
            }
        }

        // ---- A-tile change ----
        if (more && IBn != IB) {
            flush_acc(acc, IB * TM + warpM * 64, lane);
            __syncthreads();                 // all warps done reading sA
            loadA(sA, IBn * TM, tid);
            CP_COMMIT();
        }
        if (more) { IB = IBn; jb = jbn; }
        CP_WAIT0();
        __syncthreads();
    }

    flush_acc(acc, IB * TM + warpM * 64, lane);
}

// ---------------------------------------------------------------------------
__global__ void __launch_bounds__(1024) loss_kernel(float* __restrict__ out) {
    const float E2 = 7.3890560989306495f;
    float acc = 0.0f;
    for (int i = threadIdx.x; i < NROWS; i += 1024)
        acc += logf(g_rowsum[i] - E2 + 1e-8f) - g_pos[i];
    #pragma unroll
    for (int off = 16; off; off >>= 1)
        acc += __shfl_xor_sync(0xffffffffu, acc, off);
    __shared__ float sh[32];
    if ((threadIdx.x & 31) == 0) sh[threadIdx.x >> 5] = acc;
    __syncthreads();
    if (threadIdx.x == 0) {
        float t = 0.f;
        #pragma unroll
        for (int i = 0; i < 32; ++i) t += sh[i];
        out[0] = t * (1.0f / (float)NROWS);
    }
}

// ---------------------------------------------------------------------------
extern "C" void kernel_launch(void* const* d_in, const int* in_sizes, int n_in,
                              void* d_out, int out_size) {
    const float* z1 = (const float*)d_in[0];
    const float* z2 = (const float*)d_in[1];
    float* out = (float*)d_out;

    prep_kernel<<<NROWS / 2 / 4, 256>>>(z1, z2);

    cudaFuncSetAttribute(gemm_kernel, cudaFuncAttributeMaxDynamicSharedMemorySize, SMEM_DYN);
    gemm_kernel<<<GRID, 512, SMEM_DYN>>>();

    loss_kernel<<<1, 1024>>>(out);
}

// round 8
// speedup vs baseline: 1.9594x; 1.0525x over previous
#include <cuda_runtime.h>
#include <cuda_bf16.h>
#include <cstdint>

// z1, z2: (4096, 256) fp32. Interleaved normalized Z: (8192, 256), quantized e4m3
// with exp scale folded in: q = sqrt(2/ln2) * z_hat, so dot_q = (2/ln2) * dot.
// loss = mean_i [ log(sum_j exp(2 z_i.z_j) - e^2 + 1e-8) - 2 z_i.z_{i^1} ]
// Symmetric: tile (IB, jb) computed iff jb >= 4*IB (A block = 256 rows,
// B block = 64 cols). Transpose term via column sums, per 128-row half,
// iff 4*IB + 2*half < (jb & ~3) -> every ordered 64-block pair counted once.
#define D        256
#define NROWS    8192
#define RB       256              // row bytes (e4m3)
#define TM       256              // CTA tile rows (i)
#define TN       64               // CTA tile cols (j)
#define NJB      (NROWS / TN)     // 128
#define NTASK    2112             // sum_{IB=0}^{31} (128 - 4*IB)
#define GRID     148
#define ABYTES   (TM * RB)        // 65536
#define BBYTES   (TN * RB)        // 16384
#define SMEM_DYN (1024 + ABYTES + 2 * BBYTES)   // 99328

#define QSCALE   1.6986436f       // sqrt(2 / ln 2)

__device__ __align__(16) uint8_t g_Zq[NROWS * RB];   // e4m3 scaled normalized rows
__device__ float g_pos[NROWS];
__device__ float g_rowsum[NROWS];

// ---------------------------------------------------------------------------
__device__ __forceinline__ uint32_t smem_u32(const void* p) {
    uint32_t a;
    asm("{ .reg .u64 t; cvta.to.shared.u64 t, %1; cvt.u32.u64 %0, t; }" : "=r"(a) : "l"(p));
    return a;
}
__device__ __forceinline__ float ex2(float x) {
    float y; asm("ex2.approx.f32 %0, %1;" : "=f"(y) : "f"(x)); return y;
}
__device__ __forceinline__ void cpa16(uint32_t dst, const void* src) {
    asm volatile("cp.async.cg.shared.global [%0], [%1], 16;" :: "r"(dst), "l"(src) : "memory");
}
#define CP_COMMIT() asm volatile("cp.async.commit_group;" ::: "memory")
#define CP_WAIT0()  asm volatile("cp.async.wait_group 0;" ::: "memory")

#define LDSM_X4(R, ADDR)                                                         \
    asm volatile("ldmatrix.sync.aligned.m8n8.x4.shared.b16 {%0,%1,%2,%3}, [%4];" \
                 : "=r"((R)[0]), "=r"((R)[1]), "=r"((R)[2]), "=r"((R)[3])        \
                 : "r"(ADDR))

__device__ __forceinline__ void mma_e4m3(float* c, const uint32_t* a, uint32_t b0, uint32_t b1) {
    asm volatile(
        "mma.sync.aligned.m16n8k32.row.col.f32.e4m3.e4m3.f32 "
        "{%0,%1,%2,%3}, {%4,%5,%6,%7}, {%8,%9}, {%0,%1,%2,%3};"
        : "+f"(c[0]), "+f"(c[1]), "+f"(c[2]), "+f"(c[3])
        : "r"(a[0]), "r"(a[1]), "r"(a[2]), "r"(a[3]), "r"(b0), "r"(b1));
}

// SW128-style swizzled tile addressing. Atom = 8 rows x 128B.
// A tile: 256 rows (32 atom-rows); B tile: 64 rows (8 atom-rows).
__device__ __forceinline__ uint32_t taddrA(int r, int b) {
    uint32_t off = ((uint32_t)(r >> 3) + ((uint32_t)(b >> 7) << 5)) * 1024u
                 + (uint32_t)(r & 7) * 128u + (uint32_t)(b & 127);
    return off ^ ((off >> 3) & 0x70);
}
__device__ __forceinline__ uint32_t taddrB(int r, int b) {
    uint32_t off = ((uint32_t)(r >> 3) + ((uint32_t)(b >> 7) << 3)) * 1024u
                 + (uint32_t)(r & 7) * 128u + (uint32_t)(b & 127);
    return off ^ ((off >> 3) & 0x70);
}

// B tile: 64 rows x 256B = 1024 x 16B chunks; 512 threads -> 2 each.
__device__ __forceinline__ void loadB(uint32_t sdst, int row0, int tid) {
    #pragma unroll
    for (int it = 0; it < 2; ++it) {
        int idx = tid + it * 512;
        int r = idx >> 4, g = idx & 15;
        cpa16(sdst + taddrB(r, g * 16), g_Zq + (size_t)(row0 + r) * RB + g * 16);
    }
}
// A tile: 256 rows -> 4096 chunks; 8 per thread.
__device__ __forceinline__ void loadA(uint32_t sdst, int row0, int tid) {
    #pragma unroll
    for (int it = 0; it < 8; ++it) {
        int idx = tid + it * 512;
        int r = idx >> 4, g = idx & 15;
        cpa16(sdst + taddrA(r, g * 16), g_Zq + (size_t)(row0 + r) * RB + g * 16);
    }
}

// ---------------------------------------------------------------------------
// prep: one warp per pair. fp32 normalize, exact fp32 log(pos), e4m3 quantize
// with QSCALE folded in.
// ---------------------------------------------------------------------------
__device__ __forceinline__ uint32_t pack4_e4m3(float f0, float f1, float f2, float f3) {
    uint16_t lo, hi;
    asm("cvt.rn.satfinite.e4m3x2.f32 %0, %1, %2;" : "=h"(lo) : "f"(f1), "f"(f0));
    asm("cvt.rn.satfinite.e4m3x2.f32 %0, %1, %2;" : "=h"(hi) : "f"(f3), "f"(f2));
    return (uint32_t)lo | ((uint32_t)hi << 16);
}

__global__ void __launch_bounds__(256) prep_kernel(const float* __restrict__ z1,
                                                   const float* __restrict__ z2) {
    const int p    = blockIdx.x * 8 + (threadIdx.x >> 5);
    const int lane = threadIdx.x & 31;
    const float4* p1 = reinterpret_cast<const float4*>(z1 + (size_t)p * D) + lane * 2;
    const float4* p2 = reinterpret_cast<const float4*>(z2 + (size_t)p * D) + lane * 2;
    float4 a0 = p1[0], a1 = p1[1];
    float4 b0 = p2[0], b1 = p2[1];
    float s1 = a0.x*a0.x + a0.y*a0.y + a0.z*a0.z + a0.w*a0.w
             + a1.x*a1.x + a1.y*a1.y + a1.z*a1.z + a1.w*a1.w;
    float s2 = b0.x*b0.x + b0.y*b0.y + b0.z*b0.z + b0.w*b0.w
             + b1.x*b1.x + b1.y*b1.y + b1.z*b1.z + b1.w*b1.w;
    float s3 = a0.x*b0.x + a0.y*b0.y + a0.z*b0.z + a0.w*b0.w
             + a1.x*b1.x + a1.y*b1.y + a1.z*b1.z + a1.w*b1.w;
    #pragma unroll
    for (int off = 16; off; off >>= 1) {
        s1 += __shfl_xor_sync(0xffffffffu, s1, off);
        s2 += __shfl_xor_sync(0xffffffffu, s2, off);
        s3 += __shfl_xor_sync(0xffffffffu, s3, off);
    }
    float inv1 = 1.0f / fmaxf(sqrtf(s1), 1e-12f);
    float inv2 = 1.0f / fmaxf(sqrtf(s2), 1e-12f);
    if (lane == 0) {
        float lp = 2.0f * (s3 * inv1 * inv2);
        g_pos[2*p] = lp; g_pos[2*p+1] = lp;
        g_rowsum[2*p] = 0.0f; g_rowsum[2*p+1] = 0.0f;
    }
    const float q1 = inv1 * QSCALE, q2 = inv2 * QSCALE;
    uint2 qa, qb;
    qa.x = pack4_e4m3(a0.x*q1, a0.y*q1, a0.z*q1, a0.w*q1);
    qa.y = pack4_e4m3(a1.x*q1, a1.y*q1, a1.z*q1, a1.w*q1);
    qb.x = pack4_e4m3(b0.x*q2, b0.y*q2, b0.z*q2, b0.w*q2);
    qb.y = pack4_e4m3(b1.x*q2, b1.y*q2, b1.z*q2, b1.w*q2);
    *reinterpret_cast<uint2*>(g_Zq + (size_t)(2*p)   * RB + lane * 8) = qa;
    *reinterpret_cast<uint2*>(g_Zq + (size_t)(2*p+1) * RB + lane * 8) = qb;
}

// ---------------------------------------------------------------------------
// Persistent symmetric fp8 GEMM + exp + row/col reduce.
// CTA: 256(i) x 64(j) tiles, K=256. 16 warps, warp tile 64x16 (grid 4m x 4n).
// Task (IB, jb) computed iff jb >= 4*IB.
// ---------------------------------------------------------------------------
extern __shared__ char smem_raw[];

__device__ __forceinline__ void flush_acc(float* acc, int rowbase, int lane) {
    #pragma unroll
    for (int m = 0; m < 8; ++m) {
        float v = acc[m];
        v += __shfl_xor_sync(0xffffffffu, v, 1);
        v += __shfl_xor_sync(0xffffffffu, v, 2);
        if ((lane & 3) == 0)
            atomicAdd(&g_rowsum[rowbase + (m >> 1) * 16 + (m & 1) * 8 + (lane >> 2)], v);
        acc[m] = 0.0f;
    }
}

__global__ void __launch_bounds__(512, 1) gemm_kernel() {
    const uint32_t base = smem_u32(smem_raw);
    const uint32_t sb   = (base + 1023u) & ~1023u;
    const uint32_t sA   = sb;
    const uint32_t sB0  = sA + ABYTES;
    const uint32_t sB1  = sB0 + BBYTES;

    const int tid   = threadIdx.x;
    const int lane  = tid & 31;
    const int wid   = tid >> 5;
    const int warpM = wid & 3;        // 0..3 -> 64-row stripe
    const int warpN = wid >> 2;       // 0..3 -> 16-col stripe
    const int half  = warpM >> 1;     // 0: rows in 128-block 2*IB, 1: 2*IB+1

    uint32_t aAddr[4];
    {
        int rr  = warpM * 64 + (lane & 15);
        int sub = (lane >> 4) * 16;
        #pragma unroll
        for (int ma = 0; ma < 4; ++ma) aAddr[ma] = sA + taddrA(rr + ma * 16, sub);
    }
    uint32_t bOff;
    {
        int jo  = (lane & 7) + ((lane >> 4) << 3);
        int sub = ((lane >> 3) & 1) * 16;
        bOff = taddrB(warpN * 16 + jo, sub);
    }

    const int beg = (blockIdx.x * NTASK) / GRID;
    const int end = ((blockIdx.x + 1) * NTASK) / GRID;

    // decode beg -> (IB, jb): row IB has (128 - 4*IB) tasks, jb from 4*IB to 127
    int IB = 0, rem = beg;
    while (rem >= NJB - 4 * IB) { rem -= NJB - 4 * IB; ++IB; }
    int jb = 4 * IB + rem;

    loadA(sA, IB * TM, tid);  CP_COMMIT();
    loadB(sB0, jb * TN, tid); CP_COMMIT();
    CP_WAIT0();
    __syncthreads();

    float acc[8] = {0.f, 0.f, 0.f, 0.f, 0.f, 0.f, 0.f, 0.f};

    for (int t = beg; t < end; ++t) {
        const int buf = (t - beg) & 1;
        int IBn = IB, jbn = jb + 1;
        if (jbn == NJB) { IBn = IB + 1; jbn = 4 * IBn; }
        const bool more = (t + 1 < end);
        if (more) { loadB(buf ? sB0 : sB1, jbn * TN, tid); CP_COMMIT(); }

        // ---- compute tile on buffer `buf` ----
        const uint32_t bb = buf ? sB1 : sB0;
        float c[4][2][4];
        #pragma unroll
        for (int ma = 0; ma < 4; ++ma)
            #pragma unroll
            for (int na = 0; na < 2; ++na)
                #pragma unroll
                for (int q = 0; q < 4; ++q) c[ma][na][q] = 0.0f;

        #pragma unroll
        for (int ks = 0; ks < 8; ++ks) {
            const uint32_t koA = (uint32_t)((ks & 3) * 32 + (ks >> 2) * 32768);
            const uint32_t koB = (uint32_t)((ks & 3) * 32 + (ks >> 2) * 8192);
            uint32_t a[4][4];
            #pragma unroll
            for (int ma = 0; ma < 4; ++ma) LDSM_X4(a[ma], aAddr[ma] + koA);
            uint32_t b[4];
            LDSM_X4(b, bb + bOff + koB);
            #pragma unroll
            for (int ma = 0; ma < 4; ++ma) {
                mma_e4m3(c[ma][0], a[ma], b[0], b[1]);
                mma_e4m3(c[ma][1], a[ma], b[2], b[3]);
            }
        }

        // ---- epilogue: E = 2^c (scale folded); rows always; cols iff needed ----
        const bool doCols = (4 * IB + 2 * half) < (jb & ~3);
        float cs[2][2] = {{0.f, 0.f}, {0.f, 0.f}};
        #pragma unroll
        for (int ma = 0; ma < 4; ++ma) {
            #pragma unroll
            for (int na = 0; na < 2; ++na) {
                float e0 = ex2(c[ma][na][0]);
                float e1 = ex2(c[ma][na][1]);
                float e2 = ex2(c[ma][na][2]);
                float e3 = ex2(c[ma][na][3]);
                acc[ma * 2 + 0] += e0 + e1;      // row g
                acc[ma * 2 + 1] += e2 + e3;      // row g+8
                if (doCols) {
                    cs[na][0] += e0 + e2;        // col 2t
                    cs[na][1] += e1 + e3;        // col 2t+1
                }
            }
        }
        if (doCols) {
            #pragma unroll
            for (int na = 0; na < 2; ++na) {
                float v0 = cs[na][0], v1 = cs[na][1];
                #pragma unroll
                for (int off = 4; off < 32; off <<= 1) {
                    v0 += __shfl_xor_sync(0xffffffffu, v0, off);
                    v1 += __shfl_xor_sync(0xffffffffu, v1, off);
                }
                if (lane < 4) {
                    int j = jb * TN + warpN * 16 + na * 8 + 2 * lane;
                    atomicAdd(&g_rowsum[j],     v0);
                    atomicAdd(&g_rowsum[j + 1], v1);
                }
            }
        }

        // ---- A-tile change ----
        if (more && IBn != IB) {
            flush_acc(acc, IB * TM + warpM * 64, lane);
            __syncthreads();                 // all warps done reading sA
            loadA(sA, IBn * TM, tid);
            CP_COMMIT();
        }
        if (more) { IB = IBn; jb = jbn; }
        CP_WAIT0();
        __syncthreads();
    }

    flush_acc(acc, IB * TM + warpM * 64, lane);
}

// ---------------------------------------------------------------------------
__global__ void __launch_bounds__(1024) loss_kernel(float* __restrict__ out) {
    const float E2 = 7.3890560989306495f;
    float acc = 0.0f;
    for (int i = threadIdx.x; i < NROWS; i += 1024)
        acc += logf(g_rowsum[i] - E2 + 1e-8f) - g_pos[i];
    #pragma unroll
    for (int off = 16; off; off >>= 1)
        acc += __shfl_xor_sync(0xffffffffu, acc, off);
    __shared__ float sh[32];
    if ((threadIdx.x & 31) == 0) sh[threadIdx.x >> 5] = acc;
    __syncthreads();
    if (threadIdx.x == 0) {
        float t = 0.f;
        #pragma unroll
        for (int i = 0; i < 32; ++i) t += sh[i];
        out[0] = t * (1.0f / (float)NROWS);
    }
}

// ---------------------------------------------------------------------------
extern "C" void kernel_launch(void* const* d_in, const int* in_sizes, int n_in,
                              void* d_out, int out_size) {
    const float* z1 = (const float*)d_in[0];
    const float* z2 = (const float*)d_in[1];
    float* out = (float*)d_out;

    prep_kernel<<<NROWS / 2 / 8, 256>>>(z1, z2);

    cudaFuncSetAttribute(gemm_kernel, cudaFuncAttributeMaxDynamicSharedMemorySize, SMEM_DYN);
    gemm_kernel<<<GRID, 512, SMEM_DYN>>>();

    loss_kernel<<<1, 1024>>>(out);
}

// round 9
// speedup vs baseline: 2.0174x; 1.0296x over previous
#include <cuda_runtime.h>
#include <cuda_bf16.h>
#include <cstdint>

// z1, z2: (4096, 256) fp32. Interleaved normalized Z: (8192, 256), quantized e4m3
// with exp scale folded in: q = sqrt(2/ln2) * z_hat, so dot_q = (2/ln2) * dot.
// loss = mean_i [ log(sum_j exp(2 z_i.z_j) - e^2 + 1e-8) - 2 z_i.z_{i^1} ]
// Symmetric: tile (IB, jb) computed iff jb >= 4*IB (A block = 256 rows,
// B block = 64 cols). Transpose term via column sums, per 128-row half,
// iff 4*IB + 2*half < (jb & ~3) -> every ordered 64-block pair counted once.
#define D        256
#define NROWS    8192
#define RB       256              // row bytes (e4m3)
#define TM       256              // CTA tile rows (i)
#define TN       64               // CTA tile cols (j)
#define NJB      (NROWS / TN)     // 128
#define NTASK    2112             // sum_{IB=0}^{31} (128 - 4*IB)
#define GRID     148
#define ABYTES   (TM * RB)        // 65536
#define BBYTES   (TN * RB)        // 16384
#define SMEM_DYN (1024 + ABYTES + 2 * BBYTES)   // 99328

#define QSCALE   1.6986436f       // sqrt(2 / ln 2)

__device__ __align__(16) uint8_t g_Zq[NROWS * RB];   // e4m3 scaled normalized rows
__device__ float g_pos[NROWS];
__device__ float g_rowsum[NROWS];

// ---------------------------------------------------------------------------
__device__ __forceinline__ uint32_t smem_u32(const void* p) {
    uint32_t a;
    asm("{ .reg .u64 t; cvta.to.shared.u64 t, %1; cvt.u32.u64 %0, t; }" : "=r"(a) : "l"(p));
    return a;
}
__device__ __forceinline__ float ex2(float x) {
    float y; asm("ex2.approx.f32 %0, %1;" : "=f"(y) : "f"(x)); return y;
}
__device__ __forceinline__ void cpa16(uint32_t dst, const void* src) {
    asm volatile("cp.async.cg.shared.global [%0], [%1], 16;" :: "r"(dst), "l"(src) : "memory");
}
#define CP_COMMIT() asm volatile("cp.async.commit_group;" ::: "memory")
#define CP_WAIT0()  asm volatile("cp.async.wait_group 0;" ::: "memory")

#define LDSM_X4(R, ADDR)                                                         \
    asm volatile("ldmatrix.sync.aligned.m8n8.x4.shared.b16 {%0,%1,%2,%3}, [%4];" \
                 : "=r"((R)[0]), "=r"((R)[1]), "=r"((R)[2]), "=r"((R)[3])        \
                 : "r"(ADDR))

__device__ __forceinline__ void mma_e4m3(float* c, const uint32_t* a, uint32_t b0, uint32_t b1) {
    asm volatile(
        "mma.sync.aligned.m16n8k32.row.col.f32.e4m3.e4m3.f32 "
        "{%0,%1,%2,%3}, {%4,%5,%6,%7}, {%8,%9}, {%0,%1,%2,%3};"
        : "+f"(c[0]), "+f"(c[1]), "+f"(c[2]), "+f"(c[3])
        : "r"(a[0]), "r"(a[1]), "r"(a[2]), "r"(a[3]), "r"(b0), "r"(b1));
}

// SW128-style swizzled tile addressing. Atom = 8 rows x 128B.
// A tile: 256 rows (32 atom-rows); B tile: 64 rows (8 atom-rows).
__device__ __forceinline__ uint32_t taddrA(int r, int b) {
    uint32_t off = ((uint32_t)(r >> 3) + ((uint32_t)(b >> 7) << 5)) * 1024u
                 + (uint32_t)(r & 7) * 128u + (uint32_t)(b & 127);
    return off ^ ((off >> 3) & 0x70);
}
__device__ __forceinline__ uint32_t taddrB(int r, int b) {
    uint32_t off = ((uint32_t)(r >> 3) + ((uint32_t)(b >> 7) << 3)) * 1024u
                 + (uint32_t)(r & 7) * 128u + (uint32_t)(b & 127);
    return off ^ ((off >> 3) & 0x70);
}

// B tile: 64 rows x 256B = 1024 x 16B chunks; 512 threads -> 2 each.
__device__ __forceinline__ void loadB(uint32_t sdst, int row0, int tid) {
    #pragma unroll
    for (int it = 0; it < 2; ++it) {
        int idx = tid + it * 512;
        int r = idx >> 4, g = idx & 15;
        cpa16(sdst + taddrB(r, g * 16), g_Zq + (size_t)(row0 + r) * RB + g * 16);
    }
}
// A tile: 256 rows -> 4096 chunks; 8 per thread.
__device__ __forceinline__ void loadA(uint32_t sdst, int row0, int tid) {
    #pragma unroll
    for (int it = 0; it < 8; ++it) {
        int idx = tid + it * 512;
        int r = idx >> 4, g = idx & 15;
        cpa16(sdst + taddrA(r, g * 16), g_Zq + (size_t)(row0 + r) * RB + g * 16);
    }
}

// ---------------------------------------------------------------------------
// prep: one warp per pair, 128-thread blocks. All 4 float4 loads issued before
// any math (MLP=4). fp32 normalize, exact fp32 log(pos), e4m3 quantize with
// QSCALE folded in.
// ---------------------------------------------------------------------------
__device__ __forceinline__ uint32_t pack4_e4m3(float f0, float f1, float f2, float f3) {
    uint16_t lo, hi;
    asm("cvt.rn.satfinite.e4m3x2.f32 %0, %1, %2;" : "=h"(lo) : "f"(f1), "f"(f0));
    asm("cvt.rn.satfinite.e4m3x2.f32 %0, %1, %2;" : "=h"(hi) : "f"(f3), "f"(f2));
    return (uint32_t)lo | ((uint32_t)hi << 16);
}

__global__ void __launch_bounds__(128) prep_kernel(const float* __restrict__ z1,
                                                   const float* __restrict__ z2) {
    const int p    = blockIdx.x * 4 + (threadIdx.x >> 5);   // pair 0..4095
    const int lane = threadIdx.x & 31;
    const float4* __restrict__ p1 = reinterpret_cast<const float4*>(z1 + (size_t)p * D) + lane * 2;
    const float4* __restrict__ p2 = reinterpret_cast<const float4*>(z2 + (size_t)p * D) + lane * 2;
    const float4 a0 = p1[0];
    const float4 a1 = p1[1];
    const float4 b0 = p2[0];
    const float4 b1 = p2[1];
    float s1 = a0.x*a0.x + a0.y*a0.y + a0.z*a0.z + a0.w*a0.w
             + a1.x*a1.x + a1.y*a1.y + a1.z*a1.z + a1.w*a1.w;
    float s2 = b0.x*b0.x + b0.y*b0.y + b0.z*b0.z + b0.w*b0.w
             + b1.x*b1.x + b1.y*b1.y + b1.z*b1.z + b1.w*b1.w;
    float s3 = a0.x*b0.x + a0.y*b0.y + a0.z*b0.z + a0.w*b0.w
             + a1.x*b1.x + a1.y*b1.y + a1.z*b1.z + a1.w*b1.w;
    #pragma unroll
    for (int off = 16; off; off >>= 1) {
        s1 += __shfl_xor_sync(0xffffffffu, s1, off);
        s2 += __shfl_xor_sync(0xffffffffu, s2, off);
        s3 += __shfl_xor_sync(0xffffffffu, s3, off);
    }
    float inv1 = 1.0f / fmaxf(sqrtf(s1), 1e-12f);
    float inv2 = 1.0f / fmaxf(sqrtf(s2), 1e-12f);
    if (lane == 0) {
        float lp = 2.0f * (s3 * inv1 * inv2);
        g_pos[2*p] = lp; g_pos[2*p+1] = lp;
        g_rowsum[2*p] = 0.0f; g_rowsum[2*p+1] = 0.0f;
    }
    const float q1 = inv1 * QSCALE, q2 = inv2 * QSCALE;
    uint2 qa, qb;
    qa.x = pack4_e4m3(a0.x*q1, a0.y*q1, a0.z*q1, a0.w*q1);
    qa.y = pack4_e4m3(a1.x*q1, a1.y*q1, a1.z*q1, a1.w*q1);
    qb.x = pack4_e4m3(b0.x*q2, b0.y*q2, b0.z*q2, b0.w*q2);
    qb.y = pack4_e4m3(b1.x*q2, b1.y*q2, b1.z*q2, b1.w*q2);
    *reinterpret_cast<uint2*>(g_Zq + (size_t)(2*p)   * RB + lane * 8) = qa;
    *reinterpret_cast<uint2*>(g_Zq + (size_t)(2*p+1) * RB + lane * 8) = qb;
}

// ---------------------------------------------------------------------------
// Persistent symmetric fp8 GEMM + exp + row/col reduce.
// CTA: 256(i) x 64(j) tiles, K=256. 16 warps, warp tile 64x16 (grid 4m x 4n).
// Task (IB, jb) computed iff jb >= 4*IB.  (Identical to R8 - proven.)
// ---------------------------------------------------------------------------
extern __shared__ char smem_raw[];

__device__ __forceinline__ void flush_acc(float* acc, int rowbase, int lane) {
    #pragma unroll
    for (int m = 0; m < 8; ++m) {
        float v = acc[m];
        v += __shfl_xor_sync(0xffffffffu, v, 1);
        v += __shfl_xor_sync(0xffffffffu, v, 2);
        if ((lane & 3) == 0)
            atomicAdd(&g_rowsum[rowbase + (m >> 1) * 16 + (m & 1) * 8 + (lane >> 2)], v);
        acc[m] = 0.0f;
    }
}

__global__ void __launch_bounds__(512, 1) gemm_kernel() {
    const uint32_t base = smem_u32(smem_raw);
    const uint32_t sb   = (base + 1023u) & ~1023u;
    const uint32_t sA   = sb;
    const uint32_t sB0  = sA + ABYTES;
    const uint32_t sB1  = sB0 + BBYTES;

    const int tid   = threadIdx.x;
    const int lane  = tid & 31;
    const int wid   = tid >> 5;
    const int warpM = wid & 3;        // 0..3 -> 64-row stripe
    const int warpN = wid >> 2;       // 0..3 -> 16-col stripe
    const int half  = warpM >> 1;     // 0: rows in 128-block 2*IB, 1: 2*IB+1

    uint32_t aAddr[4];
    {
        int rr  = warpM * 64 + (lane & 15);
        int sub = (lane >> 4) * 16;
        #pragma unroll
        for (int ma = 0; ma < 4; ++ma) aAddr[ma] = sA + taddrA(rr + ma * 16, sub);
    }
    uint32_t bOff;
    {
        int jo  = (lane & 7) + ((lane >> 4) << 3);
        int sub = ((lane >> 3) & 1) * 16;
        bOff = taddrB(warpN * 16 + jo, sub);
    }

    const int beg = (blockIdx.x * NTASK) / GRID;
    const int end = ((blockIdx.x + 1) * NTASK) / GRID;

    // decode beg -> (IB, jb): row IB has (128 - 4*IB) tasks, jb from 4*IB to 127
    int IB = 0, rem = beg;
    while (rem >= NJB - 4 * IB) { rem -= NJB - 4 * IB; ++IB; }
    int jb = 4 * IB + rem;

    loadA(sA, IB * TM, tid);  CP_COMMIT();
    loadB(sB0, jb * TN, tid); CP_COMMIT();
    CP_WAIT0();
    __syncthreads();

    float acc[8] = {0.f, 0.f, 0.f, 0.f, 0.f, 0.f, 0.f, 0.f};

    for (int t = beg; t < end; ++t) {
        const int buf = (t - beg) & 1;
        int IBn = IB, jbn = jb + 1;
        if (jbn == NJB) { IBn = IB + 1; jbn = 4 * IBn; }
        const bool more = (t + 1 < end);
        if (more) { loadB(buf ? sB0 : sB1, jbn * TN, tid); CP_COMMIT(); }

        // ---- compute tile on buffer `buf` ----
        const uint32_t bb = buf ? sB1 : sB0;
        float c[4][2][4];
        #pragma unroll
        for (int ma = 0; ma < 4; ++ma)
            #pragma unroll
            for (int na = 0; na < 2; ++na)
                #pragma unroll
                for (int q = 0; q < 4; ++q) c[ma][na][q] = 0.0f;

        #pragma unroll
        for (int ks = 0; ks < 8; ++ks) {
            const uint32_t koA = (uint32_t)((ks & 3) * 32 + (ks >> 2) * 32768);
            const uint32_t koB = (uint32_t)((ks & 3) * 32 + (ks >> 2) * 8192);
            uint32_t a[4][4];
            #pragma unroll
            for (int ma = 0; ma < 4; ++ma) LDSM_X4(a[ma], aAddr[ma] + koA);
            uint32_t b[4];
            LDSM_X4(b, bb + bOff + koB);
            #pragma unroll
            for (int ma = 0; ma < 4; ++ma) {
                mma_e4m3(c[ma][0], a[ma], b[0], b[1]);
                mma_e4m3(c[ma][1], a[ma], b[2], b[3]);
            }
        }

        // ---- epilogue: E = 2^c (scale folded); rows always; cols iff needed ----
        const bool doCols = (4 * IB + 2 * half) < (jb & ~3);
        float cs[2][2] = {{0.f, 0.f}, {0.f, 0.f}};
        #pragma unroll
        for (int ma = 0; ma < 4; ++ma) {
            #pragma unroll
            for (int na = 0; na < 2; ++na) {
                float e0 = ex2(c[ma][na][0]);
                float e1 = ex2(c[ma][na][1]);
                float e2 = ex2(c[ma][na][2]);
                float e3 = ex2(c[ma][na][3]);
                acc[ma * 2 + 0] += e0 + e1;      // row g
                acc[ma * 2 + 1] += e2 + e3;      // row g+8
                if (doCols) {
                    cs[na][0] += e0 + e2;        // col 2t
                    cs[na][1] += e1 + e3;        // col 2t+1
                }
            }
        }
        if (doCols) {
            #pragma unroll
            for (int na = 0; na < 2; ++na) {
                float v0 = cs[na][0], v1 = cs[na][1];
                #pragma unroll
                for (int off = 4; off < 32; off <<= 1) {
                    v0 += __shfl_xor_sync(0xffffffffu, v0, off);
                    v1 += __shfl_xor_sync(0xffffffffu, v1, off);
                }
                if (lane < 4) {
                    int j = jb * TN + warpN * 16 + na * 8 + 2 * lane;
                    atomicAdd(&g_rowsum[j],     v0);
                    atomicAdd(&g_rowsum[j + 1], v1);
                }
            }
        }

        // ---- A-tile change ----
        if (more && IBn != IB) {
            flush_acc(acc, IB * TM + warpM * 64, lane);
            __syncthreads();                 // all warps done reading sA
            loadA(sA, IBn * TM, tid);
            CP_COMMIT();
        }
        if (more) { IB = IBn; jb = jbn; }
        CP_WAIT0();
        __syncthreads();
    }

    flush_acc(acc, IB * TM + warpM * 64, lane);
}

// ---------------------------------------------------------------------------
__global__ void __launch_bounds__(1024) loss_kernel(float* __restrict__ out) {
    const float E2 = 7.3890560989306495f;
    float acc = 0.0f;
    for (int i = threadIdx.x; i < NROWS; i += 1024)
        acc += __logf(g_rowsum[i] - E2 + 1e-8f) - g_pos[i];
    #pragma unroll
    for (int off = 16; off; off >>= 1)
        acc += __shfl_xor_sync(0xffffffffu, acc, off);
    __shared__ float sh[32];
    if ((threadIdx.x & 31) == 0) sh[threadIdx.x >> 5] = acc;
    __syncthreads();
    if (threadIdx.x == 0) {
        float t = 0.f;
        #pragma unroll
        for (int i = 0; i < 32; ++i) t += sh[i];
        out[0] = t * (1.0f / (float)NROWS);
    }
}

// ---------------------------------------------------------------------------
extern "C" void kernel_launch(void* const* d_in, const int* in_sizes, int n_in,
                              void* d_out, int out_size) {
    const float* z1 = (const float*)d_in[0];
    const float* z2 = (const float*)d_in[1];
    float* out = (float*)d_out;

    prep_kernel<<<NROWS / 2 / 4, 128>>>(z1, z2);

    cudaFuncSetAttribute(gemm_kernel, cudaFuncAttributeMaxDynamicSharedMemorySize, SMEM_DYN);
    gemm_kernel<<<GRID, 512, SMEM_DYN>>>();

    loss_kernel<<<1, 1024>>>(out);
}